// round 10
// baseline (speedup 1.0000x reference)
#include <cuda_runtime.h>
#include <cuda_bf16.h>
#include <cstdint>

#define N_NODES 100000
#define N_EDGES 1000000
#define IN_CH   32
#define EDGE_CH 16
#define OUT_CH  32
#define D_MID   56
#define TILE_E  64
#define NTILES  ((N_EDGES + TILE_E - 1) / TILE_E)

typedef unsigned int u32;
typedef unsigned long long u64;

// ---- device globals ---------------------------------------------------------
static __device__ int g_is64;
static __device__ __align__(16) float g_XR[N_NODES * D_MID];  // x@W1[0:32]+b1
static __device__ __align__(16) float g_XC[N_NODES * D_MID];  // x@W1[32:64]
static __device__ __align__(16) u32 g_w1eh[504];  // W1e [56n][9w] (k pairs), hi
static __device__ __align__(16) u32 g_w1el[504];  // lo
static __device__ __align__(16) __nv_bfloat16 g_w2hi[OUT_CH * 64]; // [n][k pad 64]
static __device__ __align__(16) __nv_bfloat16 g_w2lo[OUT_CH * 64];

// ---- packed f32x2 helpers (scalar k_node) ------------------------------------
__device__ __forceinline__ u64 pk2(float a, float b) {
    u64 r; asm("mov.b64 %0, {%1,%2};" : "=l"(r) : "f"(a), "f"(b)); return r;
}
#define FMA2(d, a, b, c) asm("fma.rn.f32x2 %0, %1, %2, %3;" : "=l"(d) : "l"(a), "l"(b), "l"(c))

// ---- mma helpers --------------------------------------------------------------
__device__ __forceinline__ void mma16816(float d[4], const u32 a[4], u32 b0, u32 b1) {
    asm volatile(
        "mma.sync.aligned.m16n8k16.row.col.f32.bf16.bf16.f32 "
        "{%0,%1,%2,%3}, {%4,%5,%6,%7}, {%8,%9}, {%0,%1,%2,%3};\n"
        : "+f"(d[0]), "+f"(d[1]), "+f"(d[2]), "+f"(d[3])
        : "r"(a[0]), "r"(a[1]), "r"(a[2]), "r"(a[3]), "r"(b0), "r"(b1));
}
__device__ __forceinline__ u32 pack_split(float v0, float v1, u32& lo) {
    __nv_bfloat16 h0 = __float2bfloat16(v0), h1 = __float2bfloat16(v1);
    float f0 = __bfloat162float(h0), f1 = __bfloat162float(h1);
    __nv_bfloat16 l0 = __float2bfloat16(v0 - f0), l1 = __float2bfloat16(v1 - f1);
    lo = (u32)__bfloat16_as_ushort(l0) | ((u32)__bfloat16_as_ushort(l1) << 16);
    return (u32)__bfloat16_as_ushort(h0) | ((u32)__bfloat16_as_ushort(h1) << 16);
}
__device__ __forceinline__ void atomicMaxF(float* addr, float val) {
    if (val >= 0.0f) atomicMax(reinterpret_cast<int*>(addr), __float_as_int(val));
    else             atomicMin(reinterpret_cast<unsigned int*>(addr), __float_as_uint(val));
}

// ---------------------------------------------------------------------------
// K0: init out to -inf, detect int64, pack W1e (rows 64..79) + W2 hi/lo
// ---------------------------------------------------------------------------
__global__ void k_pre(const unsigned int* __restrict__ widx,
                      const float* __restrict__ W1,
                      const float* __restrict__ W2,
                      unsigned int* __restrict__ out) {
    if (blockIdx.x == 0) {
        __shared__ int bad;
        if (threadIdx.x == 0) bad = 0;
        __syncthreads();
        for (int i = threadIdx.x; i < 4096; i += blockDim.x)
            if (widx[2 * i + 1] != 0u) bad = 1;   // benign race
        __syncthreads();
        if (threadIdx.x == 0) g_is64 = !bad;
    }
    if (blockIdx.x == 1) {  // W1e: [56 n][9 words], word j = bf16 pair (k=2j, 2j+1)
        for (int i = threadIdx.x; i < D_MID * 9; i += blockDim.x) {
            int n = i / 9, j = i % 9;
            u32 hi = 0, lo = 0;
            if (j < 8) {
                float v0 = W1[(64 + 2 * j) * D_MID + n];
                float v1 = W1[(64 + 2 * j + 1) * D_MID + n];
                hi = pack_split(v0, v1, lo);
            }
            g_w1eh[i] = hi;
            g_w1el[i] = lo;
        }
    }
    if (blockIdx.x == 2) {  // W2 [56][32] -> [n][k pad 64] hi/lo
        for (int i = threadIdx.x; i < OUT_CH * 64; i += blockDim.x) {
            int n = i / 64, k = i % 64;
            float v = (k < D_MID) ? W2[k * OUT_CH + n] : 0.0f;
            __nv_bfloat16 h = __float2bfloat16(v);
            g_w2hi[i] = h;
            g_w2lo[i] = __float2bfloat16(v - __bfloat162float(h));
        }
    }
    int stride = gridDim.x * blockDim.x;
    for (int i = blockIdx.x * blockDim.x + threadIdx.x; i < N_NODES * OUT_CH; i += stride)
        out[i] = 0xFF800000u;  // -inf
}

// ---------------------------------------------------------------------------
// K1: per-node precompute (scalar fp32, j-blocked, proven in R6)
// ---------------------------------------------------------------------------
__global__ void __launch_bounds__(128, 8) k_node(const float* __restrict__ x,
                                                 const float* __restrict__ W1,
                                                 const float* __restrict__ b1) {
    __shared__ __align__(16) float sW[2 * IN_CH * D_MID];
    __shared__ __align__(16) float sb[D_MID];
    for (int i = threadIdx.x; i < 2 * IN_CH * D_MID; i += blockDim.x) sW[i] = W1[i];
    for (int i = threadIdx.x; i < D_MID; i += blockDim.x) sb[i] = b1[i];
    __syncthreads();

    int n = blockIdx.x * blockDim.x + threadIdx.x;
    if (n >= N_NODES) return;

    float xr[IN_CH];
    const float4* xp = reinterpret_cast<const float4*>(x + n * IN_CH);
#pragma unroll
    for (int c = 0; c < 8; c++) {
        float4 v = xp[c];
        xr[4 * c + 0] = v.x; xr[4 * c + 1] = v.y; xr[4 * c + 2] = v.z; xr[4 * c + 3] = v.w;
    }

#pragma unroll
    for (int which = 0; which < 2; which++) {
        float* dstbase = (which == 0 ? g_XR : g_XC) + (size_t)n * D_MID;
        const float* Wbase = sW + which * IN_CH * D_MID;
#pragma unroll
        for (int jb = 0; jb < D_MID / 8; jb++) {
            u64 hb0, hb1, hb2, hb3;
            if (which == 0) {
                const ulonglong2* bp = reinterpret_cast<const ulonglong2*>(&sb[8 * jb]);
                ulonglong2 b01 = bp[0], b23 = bp[1];
                hb0 = b01.x; hb1 = b01.y; hb2 = b23.x; hb3 = b23.y;
            } else {
                hb0 = hb1 = hb2 = hb3 = 0ull;
            }
#pragma unroll
            for (int k = 0; k < IN_CH; k++) {
                u64 aa = pk2(xr[k], xr[k]);
                const ulonglong2* w = reinterpret_cast<const ulonglong2*>(Wbase + k * D_MID + 8 * jb);
                ulonglong2 w0 = w[0], w1 = w[1];
                FMA2(hb0, aa, w0.x, hb0);
                FMA2(hb1, aa, w0.y, hb1);
                FMA2(hb2, aa, w1.x, hb2);
                FMA2(hb3, aa, w1.y, hb3);
            }
            ulonglong2* dst = reinterpret_cast<ulonglong2*>(dstbase + 8 * jb);
            ulonglong2 s0; s0.x = hb0; s0.y = hb1;
            ulonglong2 s1; s1.x = hb2; s1.y = hb3;
            dst[0] = s0; dst[1] = s1;
        }
    }
}

// ---------------------------------------------------------------------------
// K2: persistent hybrid edge kernel.
// smem words: XRC fp32 [64][60] @0 (reused as H_hi[64][36]@0 / H_lo@2304),
//             W1e_hi@4608 (504), W1e_lo@5112, ea_hi@5616 ([64][10]), ea_lo@6256.
// ---------------------------------------------------------------------------
#define XRC   0
#define HHI   0
#define HLO   2304
#define W1EH  4608
#define W1EL  5112
#define SEAH  5616
#define SEAL  6256
#define SMW   6896

__global__ void __launch_bounds__(128) k_edge(const int* __restrict__ idx32,
                                              const float* __restrict__ ea,
                                              const float* __restrict__ b2,
                                              float* __restrict__ out) {
    __shared__ u32 sm[SMW];
    __shared__ int srol[TILE_E], scol[TILE_E];

    const int tid  = threadIdx.x;
    const int w    = tid >> 5;
    const int lane = tid & 31;
    const int g    = lane >> 2;
    const int t    = lane & 3;

    // W1e tiles into smem once
    for (int i = tid; i < 504; i += 128) {
        sm[W1EH + i] = g_w1eh[i];
        sm[W1EL + i] = g_w1el[i];
    }
    // hoist b2 fragments
    float bb2[4][2];
#pragma unroll
    for (int nt = 0; nt < 4; nt++) {
        bb2[nt][0] = __ldg(&b2[nt * 8 + 2 * t]);
        bb2[nt][1] = __ldg(&b2[nt * 8 + 2 * t + 1]);
    }
    const int is64 = g_is64;
    const int el   = tid >> 1;       // edge owned for staging
    const int half = tid & 1;

    for (int tile = blockIdx.x; tile < NTILES; tile += gridDim.x) {
        const int ebase = tile * TILE_E;

        __syncthreads();   // previous tile fully consumed
        if (tid < TILE_E) {
            int e = ebase + tid;
            if (e > N_EDGES - 1) e = N_EDGES - 1;
            int r, c;
            if (is64) { r = idx32[2 * e];  c = idx32[2 * (N_EDGES + e)]; }
            else      { r = idx32[e];      c = idx32[N_EDGES + e]; }
            srol[tid] = r; scol[tid] = c;
        }
        __syncthreads();

        // ---- stage XRC = XR[rol] + XC[col]  (fp32, 2 threads per edge) ----
        {
            int r = srol[el], c = scol[el];
            const float4* pr = reinterpret_cast<const float4*>(g_XR + (size_t)r * D_MID) + half * 7;
            const float4* pc = reinterpret_cast<const float4*>(g_XC + (size_t)c * D_MID) + half * 7;
            float4* dst = reinterpret_cast<float4*>(sm + XRC + el * 60 + half * 28);
#pragma unroll
            for (int q = 0; q < 7; q++) {
                float4 a = pr[q], b = pc[q];
                a.x += b.x; a.y += b.y; a.z += b.z; a.w += b.w;
                dst[q] = a;
            }
        }
        // ---- stage ea -> bf16 hi/lo ----
        {
            int ec = ebase + el; if (ec > N_EDGES - 1) ec = N_EDGES - 1;
            const float4* pe = reinterpret_cast<const float4*>(ea + (size_t)ec * EDGE_CH + half * 8);
            float4 v0 = pe[0], v1 = pe[1];
            u32 lo0, lo1, lo2, lo3;
            u32 h0 = pack_split(v0.x, v0.y, lo0);
            u32 h1 = pack_split(v0.z, v0.w, lo1);
            u32 h2 = pack_split(v1.x, v1.y, lo2);
            u32 h3 = pack_split(v1.z, v1.w, lo3);
            u32 bo = el * 10 + half * 4;
            sm[SEAH + bo + 0] = h0;  sm[SEAH + bo + 1] = h1;
            sm[SEAH + bo + 2] = h2;  sm[SEAH + bo + 3] = h3;
            sm[SEAL + bo + 0] = lo0; sm[SEAL + bo + 1] = lo1;
            sm[SEAL + bo + 2] = lo2; sm[SEAL + bo + 3] = lo3;
        }
        __syncthreads();

        // ---- layer 1: acc = ea @ W1e (3-pass) + XRC fragment add ----
        float acc[7][4];
#pragma unroll
        for (int nt = 0; nt < 7; nt++) {
            acc[nt][0] = 0.f; acc[nt][1] = 0.f; acc[nt][2] = 0.f; acc[nt][3] = 0.f;
        }
        {
            u32 ah[4], al[4];
            ah[0] = sm[SEAH + g * 10 + t];        ah[1] = sm[SEAH + (g + 8) * 10 + t];
            ah[2] = sm[SEAH + g * 10 + t + 4];    ah[3] = sm[SEAH + (g + 8) * 10 + t + 4];
            al[0] = sm[SEAL + g * 10 + t];        al[1] = sm[SEAL + (g + 8) * 10 + t];
            al[2] = sm[SEAL + g * 10 + t + 4];    al[3] = sm[SEAL + (g + 8) * 10 + t + 4];
            // rows here are edges (w*16+g handled below via fragment row mapping):
            // NOTE: A rows for this warp are edges w*16+g and w*16+g+8
            ah[0] = sm[SEAH + (w * 16 + g) * 10 + t];
            ah[1] = sm[SEAH + (w * 16 + g + 8) * 10 + t];
            ah[2] = sm[SEAH + (w * 16 + g) * 10 + t + 4];
            ah[3] = sm[SEAH + (w * 16 + g + 8) * 10 + t + 4];
            al[0] = sm[SEAL + (w * 16 + g) * 10 + t];
            al[1] = sm[SEAL + (w * 16 + g + 8) * 10 + t];
            al[2] = sm[SEAL + (w * 16 + g) * 10 + t + 4];
            al[3] = sm[SEAL + (w * 16 + g + 8) * 10 + t + 4];
#pragma unroll
            for (int nt = 0; nt < 7; nt++) {
                int bro = (nt * 8 + g) * 9 + t;
                u32 bh0 = sm[W1EH + bro], bh1 = sm[W1EH + bro + 4];
                u32 bl0 = sm[W1EL + bro], bl1 = sm[W1EL + bro + 4];
                mma16816(acc[nt], ah, bh0, bh1);
                mma16816(acc[nt], ah, bl0, bl1);
                mma16816(acc[nt], al, bh0, bh1);
            }
        }
        // fragment add of XRC + LeakyReLU
        {
            const float2* x0 = reinterpret_cast<const float2*>(sm + XRC + (w * 16 + g) * 60);
            const float2* x1 = reinterpret_cast<const float2*>(sm + XRC + (w * 16 + g + 8) * 60);
#pragma unroll
            for (int nt = 0; nt < 7; nt++) {
                float2 u = x0[nt * 4 + t];
                float2 v = x1[nt * 4 + t];
                float a0 = acc[nt][0] + u.x, a1 = acc[nt][1] + u.y;
                float a2 = acc[nt][2] + v.x, a3 = acc[nt][3] + v.y;
                acc[nt][0] = fmaxf(a0, 0.01f * a0);
                acc[nt][1] = fmaxf(a1, 0.01f * a1);
                acc[nt][2] = fmaxf(a2, 0.01f * a2);
                acc[nt][3] = fmaxf(a3, 0.01f * a3);
            }
        }
        __syncthreads();   // all warps done reading XRC/sea before H overwrite

        // ---- write H hi/lo (stride 36 words), zero pad k=56..63 ----
        {
            const int hr0 = (w * 16 + g) * 36;
            const int hr1 = (w * 16 + g + 8) * 36;
#pragma unroll
            for (int nt = 0; nt < 7; nt++) {
                u32 lo, hi;
                hi = pack_split(acc[nt][0], acc[nt][1], lo);
                sm[HHI + hr0 + nt * 4 + t] = hi;
                sm[HLO + hr0 + nt * 4 + t] = lo;
                hi = pack_split(acc[nt][2], acc[nt][3], lo);
                sm[HHI + hr1 + nt * 4 + t] = hi;
                sm[HLO + hr1 + nt * 4 + t] = lo;
            }
#pragma unroll
            for (int z = 0; z < 2; z++) {
                int r = w * 16 + (lane >> 1);
                int wd = 28 + (lane & 1) * 2 + z;
                sm[HHI + r * 36 + wd] = 0;
                sm[HLO + r * 36 + wd] = 0;
            }
        }
        __syncwarp();      // layer 2 reads only this warp's H rows

        // ---- layer 2: O = H @ W2 + b2 (3-pass) ----
        float o[4][4];
#pragma unroll
        for (int nt = 0; nt < 4; nt++) {
            o[nt][0] = bb2[nt][0]; o[nt][1] = bb2[nt][1];
            o[nt][2] = bb2[nt][0]; o[nt][3] = bb2[nt][1];
        }
        {
            const int hr0 = (w * 16 + g) * 36;
            const int hr1 = (w * 16 + g + 8) * 36;
#pragma unroll
            for (int ks = 0; ks < 4; ks++) {
                int c0 = ks * 8 + t, c1 = c0 + 4;
                u32 ahi[4], alo[4];
                ahi[0] = sm[HHI + hr0 + c0]; ahi[1] = sm[HHI + hr1 + c0];
                ahi[2] = sm[HHI + hr0 + c1]; ahi[3] = sm[HHI + hr1 + c1];
                alo[0] = sm[HLO + hr0 + c0]; alo[1] = sm[HLO + hr1 + c0];
                alo[2] = sm[HLO + hr0 + c1]; alo[3] = sm[HLO + hr1 + c1];
#pragma unroll
                for (int nt = 0; nt < 4; nt++) {
                    const u32* w2h = reinterpret_cast<const u32*>(g_w2hi + (nt * 8 + g) * 64);
                    const u32* w2l = reinterpret_cast<const u32*>(g_w2lo + (nt * 8 + g) * 64);
                    u32 bh0 = __ldg(&w2h[ks * 8 + t]), bh1 = __ldg(&w2h[ks * 8 + t + 4]);
                    u32 bl0 = __ldg(&w2l[ks * 8 + t]), bl1 = __ldg(&w2l[ks * 8 + t + 4]);
                    mma16816(o[nt], ahi, bh0, bh1);
                    mma16816(o[nt], ahi, bl0, bl1);
                    mma16816(o[nt], alo, bh0, bh1);
                }
            }
        }

        // ---- LeakyReLU + filtered scatter-max ----
#pragma unroll
        for (int nt = 0; nt < 4; nt++) {
            int ch = nt * 8 + 2 * t;
#pragma unroll
            for (int hf = 0; hf < 2; hf++) {
                int eL = w * 16 + g + hf * 8;
                if (ebase + eL < N_EDGES) {
                    int node = scol[eL];
                    float v0 = o[nt][hf * 2 + 0];
                    float v1 = o[nt][hf * 2 + 1];
                    v0 = fmaxf(v0, 0.01f * v0);
                    v1 = fmaxf(v1, 0.01f * v1);
                    float* p = out + (size_t)node * OUT_CH + ch;
                    float c0v = p[0], c1v = p[1];   // monotone max: stale read safe
                    if (v0 > c0v) atomicMaxF(p, v0);
                    if (v1 > c1v) atomicMaxF(p + 1, v1);
                }
            }
        }
    }
}

// ---------------------------------------------------------------------------
// K3: finalize — -inf -> 0, elementwise max with x (float4)
// ---------------------------------------------------------------------------
__global__ void k_final(const float4* __restrict__ x, float4* __restrict__ out) {
    int i = blockIdx.x * blockDim.x + threadIdx.x;
    if (i >= N_NODES * OUT_CH / 4) return;
    float4 a = out[i];
    float4 b = x[i];
    if (__float_as_uint(a.x) == 0xFF800000u) a.x = 0.0f;
    if (__float_as_uint(a.y) == 0xFF800000u) a.y = 0.0f;
    if (__float_as_uint(a.z) == 0xFF800000u) a.z = 0.0f;
    if (__float_as_uint(a.w) == 0xFF800000u) a.w = 0.0f;
    a.x = fmaxf(a.x, b.x); a.y = fmaxf(a.y, b.y);
    a.z = fmaxf(a.z, b.z); a.w = fmaxf(a.w, b.w);
    out[i] = a;
}

// ---------------------------------------------------------------------------
extern "C" void kernel_launch(void* const* d_in, const int* in_sizes, int n_in,
                              void* d_out, int out_size) {
    const float* x         = (const float*)d_in[0];
    const int*   idx32     = (const int*)d_in[1];
    const float* edge_attr = (const float*)d_in[2];
    const float* W1        = (const float*)d_in[3];
    const float* b1        = (const float*)d_in[4];
    const float* W2        = (const float*)d_in[5];
    const float* b2        = (const float*)d_in[6];
    float* out = (float*)d_out;

    k_pre<<<592, 256>>>((const unsigned int*)d_in[1], W1, W2, (unsigned int*)d_out);
    k_node<<<(N_NODES + 127) / 128, 128>>>(x, W1, b1);
    k_edge<<<592, 128>>>(idx32, edge_attr, b2, out);
    k_final<<<(N_NODES * OUT_CH / 4 + 255) / 256, 256>>>((const float4*)x, (float4*)out);
}

// round 11
// speedup vs baseline: 1.5536x; 1.5536x over previous
#include <cuda_runtime.h>
#include <cstdint>

#define N_NODES 100000
#define N_EDGES 1000000
#define IN_CH   32
#define EDGE_CH 16
#define OUT_CH  32
#define D_MID   56
#define ROW_PAD 60   // staged row stride in floats (240B)

typedef unsigned long long u64;

static __device__ int g_is64;
static __device__ __align__(16) float g_XR[N_NODES * D_MID];  // x@W1[0:32]+b1
static __device__ __align__(16) float g_XC[N_NODES * D_MID];  // x@W1[32:64]
static __device__ __align__(16) float4 g_H[14 * N_EDGES];     // H[q][e], k = 4q+u

// ---- packed f32x2 helpers ---------------------------------------------------
__device__ __forceinline__ u64 pk2(float a, float b) {
    u64 r; asm("mov.b64 %0, {%1,%2};" : "=l"(r) : "f"(a), "f"(b)); return r;
}
__device__ __forceinline__ void upk2(float& a, float& b, u64 v) {
    asm("mov.b64 {%0,%1}, %2;" : "=f"(a), "=f"(b) : "l"(v));
}
#define FMA2(d, a, b, c) asm("fma.rn.f32x2 %0, %1, %2, %3;" : "=l"(d) : "l"(a), "l"(b), "l"(c))
#define MUL2(d, a, b)    asm("mul.rn.f32x2 %0, %1, %2;"     : "=l"(d) : "l"(a), "l"(b))
#define ADD2(d, a, b)    asm("add.rn.f32x2 %0, %1, %2;"     : "=l"(d) : "l"(a), "l"(b))

__device__ __forceinline__ void atomicMaxF(float* addr, float val) {
    if (val >= 0.0f) atomicMax(reinterpret_cast<int*>(addr), __float_as_int(val));
    else             atomicMin(reinterpret_cast<unsigned int*>(addr), __float_as_uint(val));
}

// ---------------------------------------------------------------------------
// K0: init output to -inf + (block 0) detect int64 vs int32 edge_index
// ---------------------------------------------------------------------------
__global__ void k_pre(const unsigned int* __restrict__ w, unsigned int* __restrict__ out) {
    if (blockIdx.x == 0) {
        __shared__ int bad;
        if (threadIdx.x == 0) bad = 0;
        __syncthreads();
        for (int i = threadIdx.x; i < 4096; i += blockDim.x)
            if (w[2 * i + 1] != 0u) bad = 1;   // benign race
        __syncthreads();
        if (threadIdx.x == 0) g_is64 = !bad;
    }
    int stride = gridDim.x * blockDim.x;
    for (int i = blockIdx.x * blockDim.x + threadIdx.x; i < N_NODES * OUT_CH; i += stride)
        out[i] = 0xFF800000u;  // -inf
}

// ---------------------------------------------------------------------------
// K1: per-node precompute (scalar fp32, j-blocked — proven round 6)
// ---------------------------------------------------------------------------
__global__ void __launch_bounds__(128, 8) k_node(const float* __restrict__ x,
                                                 const float* __restrict__ W1,
                                                 const float* __restrict__ b1) {
    __shared__ __align__(16) float sW[2 * IN_CH * D_MID];
    __shared__ __align__(16) float sb[D_MID];
    for (int i = threadIdx.x; i < 2 * IN_CH * D_MID; i += blockDim.x) sW[i] = W1[i];
    for (int i = threadIdx.x; i < D_MID; i += blockDim.x) sb[i] = b1[i];
    __syncthreads();

    int n = blockIdx.x * blockDim.x + threadIdx.x;
    if (n >= N_NODES) return;

    float xr[IN_CH];
    const float4* xp = reinterpret_cast<const float4*>(x + n * IN_CH);
#pragma unroll
    for (int c = 0; c < 8; c++) {
        float4 v = xp[c];
        xr[4 * c + 0] = v.x; xr[4 * c + 1] = v.y; xr[4 * c + 2] = v.z; xr[4 * c + 3] = v.w;
    }

#pragma unroll
    for (int which = 0; which < 2; which++) {
        float* dstbase = (which == 0 ? g_XR : g_XC) + (size_t)n * D_MID;
        const float* Wbase = sW + which * IN_CH * D_MID;
#pragma unroll
        for (int jb = 0; jb < D_MID / 8; jb++) {
            u64 hb0, hb1, hb2, hb3;
            if (which == 0) {
                const ulonglong2* bp = reinterpret_cast<const ulonglong2*>(&sb[8 * jb]);
                ulonglong2 b01 = bp[0], b23 = bp[1];
                hb0 = b01.x; hb1 = b01.y; hb2 = b23.x; hb3 = b23.y;
            } else {
                hb0 = hb1 = hb2 = hb3 = 0ull;
            }
#pragma unroll
            for (int k = 0; k < IN_CH; k++) {
                u64 aa = pk2(xr[k], xr[k]);
                const ulonglong2* w = reinterpret_cast<const ulonglong2*>(Wbase + k * D_MID + 8 * jb);
                ulonglong2 w0 = w[0], w1 = w[1];
                FMA2(hb0, aa, w0.x, hb0);
                FMA2(hb1, aa, w0.y, hb1);
                FMA2(hb2, aa, w1.x, hb2);
                FMA2(hb3, aa, w1.y, hb3);
            }
            ulonglong2* dst = reinterpret_cast<ulonglong2*>(dstbase + 8 * jb);
            ulonglong2 s0; s0.x = hb0; s0.y = hb1;
            ulonglong2 s1; s1.x = hb2; s1.y = hb3;
            dst[0] = s0; dst[1] = s1;
        }
    }
}

// ---------------------------------------------------------------------------
// K2a: layer 1 -> H (warp-cooperative gather staging, proven round 5)
// ---------------------------------------------------------------------------
__device__ __forceinline__ void stage_rows(const float* __restrict__ table,
                                           int row, float* __restrict__ sb,
                                           int half, int sub) {
#pragma unroll
    for (int r2 = 0; r2 < 32; r2 += 2) {
        int src0 = __shfl_sync(0xffffffffu, row, r2);
        int src1 = __shfl_sync(0xffffffffu, row, r2 + 1);
        int src  = half ? src1 : src0;
        int r    = r2 + half;
        if (sub < 14) {
            float4 v = __ldg(reinterpret_cast<const float4*>(table + (size_t)src * D_MID) + sub);
            *reinterpret_cast<float4*>(sb + r * ROW_PAD + sub * 4) = v;
        }
    }
}

__global__ void __launch_bounds__(128) k_e1(const int* __restrict__ idx32,
                                            const float* __restrict__ ea,
                                            const float* __restrict__ W1) {
    __shared__ __align__(16) float sWe[EDGE_CH * D_MID];   // 3584 B
    __shared__ __align__(16) float sbuf[4][32 * ROW_PAD];  // 4 x 7680 B

    const float* We = W1 + 2 * IN_CH * D_MID;
    for (int i = threadIdx.x; i < EDGE_CH * D_MID; i += blockDim.x) sWe[i] = We[i];
    __syncthreads();

    const int warp = threadIdx.x >> 5;
    const int lane = threadIdx.x & 31;
    const int half = lane >> 4;
    const int sub  = lane & 15;
    float* sb = sbuf[warp];

    int e = blockIdx.x * 128 + warp * 32 + lane;
    bool valid = e < N_EDGES;
    int ec = valid ? e : N_EDGES - 1;

    int rol, col;
    if (g_is64) {
        rol = idx32[2 * ec];
        col = idx32[2 * (N_EDGES + ec)];
    } else {
        rol = idx32[ec];
        col = idx32[N_EDGES + ec];
    }

    // stage XR rows (LDG latency overlapped by layer-1a FMAs below)
    stage_rows(g_XR, rol, sb, half, sub);

    // h = edge_attr[ec] @ We (smem-only compute)
    u64 h[D_MID / 2];
    {
        const float4* pe = reinterpret_cast<const float4*>(ea + (size_t)ec * EDGE_CH);
        float av[EDGE_CH];
#pragma unroll
        for (int c = 0; c < 4; c++) {
            float4 v = pe[c];
            av[4 * c + 0] = v.x; av[4 * c + 1] = v.y; av[4 * c + 2] = v.z; av[4 * c + 3] = v.w;
        }
#pragma unroll
        for (int k = 0; k < EDGE_CH; k++) {
            u64 aa = pk2(av[k], av[k]);
            const ulonglong2* w = reinterpret_cast<const ulonglong2*>(&sWe[k * D_MID]);
#pragma unroll
            for (int j = 0; j < D_MID / 4; j++) {
                ulonglong2 ww = w[j];
                if (k == 0) {
                    MUL2(h[2 * j],     aa, ww.x);
                    MUL2(h[2 * j + 1], aa, ww.y);
                } else {
                    FMA2(h[2 * j],     aa, ww.x, h[2 * j]);
                    FMA2(h[2 * j + 1], aa, ww.y, h[2 * j + 1]);
                }
            }
        }
    }

    // consume XR row from smem
    __syncwarp();
    {
        const ulonglong2* pr = reinterpret_cast<const ulonglong2*>(sb + lane * ROW_PAD);
#pragma unroll
        for (int j = 0; j < D_MID / 4; j++) {
            ulonglong2 a = pr[j];
            ADD2(h[2 * j],     h[2 * j],     a.x);
            ADD2(h[2 * j + 1], h[2 * j + 1], a.y);
        }
    }
    __syncwarp();

    // stage + consume XC rows
    stage_rows(g_XC, col, sb, half, sub);
    __syncwarp();
    {
        const ulonglong2* pc = reinterpret_cast<const ulonglong2*>(sb + lane * ROW_PAD);
#pragma unroll
        for (int j = 0; j < D_MID / 4; j++) {
            ulonglong2 a = pc[j];
            ADD2(h[2 * j],     h[2 * j],     a.x);
            ADD2(h[2 * j + 1], h[2 * j + 1], a.y);
        }
    }

    // LeakyReLU + coalesced store of H (float4 per q, lane-contiguous)
    if (valid) {
#pragma unroll
        for (int q = 0; q < 14; q++) {
            float a0, a1, a2, a3;
            upk2(a0, a1, h[2 * q]);
            upk2(a2, a3, h[2 * q + 1]);
            a0 = fmaxf(a0, 0.01f * a0);
            a1 = fmaxf(a1, 0.01f * a1);
            a2 = fmaxf(a2, 0.01f * a2);
            a3 = fmaxf(a3, 0.01f * a3);
            g_H[(size_t)q * N_EDGES + e] = make_float4(a0, a1, a2, a3);
        }
    }
}

// ---------------------------------------------------------------------------
// K2b: layer 2 (streaming H) + filtered scatter-max
// ---------------------------------------------------------------------------
__global__ void __launch_bounds__(128) k_e2(const int* __restrict__ idx32,
                                            const float* __restrict__ W2,
                                            const float* __restrict__ b2,
                                            float* __restrict__ out) {
    __shared__ __align__(16) float sW2[D_MID * OUT_CH];
    __shared__ __align__(16) float sb2[OUT_CH];
    for (int i = threadIdx.x; i < D_MID * OUT_CH; i += blockDim.x) sW2[i] = W2[i];
    for (int i = threadIdx.x; i < OUT_CH; i += blockDim.x) sb2[i] = b2[i];
    __syncthreads();

    int e = blockIdx.x * 128 + threadIdx.x;
    if (e >= N_EDGES) return;

    int col = g_is64 ? idx32[2 * (N_EDGES + e)] : idx32[N_EDGES + e];

    u64 o[OUT_CH / 2];
    {
        const ulonglong2* bp = reinterpret_cast<const ulonglong2*>(sb2);
#pragma unroll
        for (int j = 0; j < OUT_CH / 4; j++) {
            ulonglong2 v = bp[j];
            o[2 * j] = v.x; o[2 * j + 1] = v.y;
        }
    }

#pragma unroll
    for (int q = 0; q < 14; q++) {
        float4 hv = g_H[(size_t)q * N_EDGES + e];
        float hs[4] = {hv.x, hv.y, hv.z, hv.w};
#pragma unroll
        for (int u = 0; u < 4; u++) {
            int k = 4 * q + u;
            u64 aa = pk2(hs[u], hs[u]);
            const ulonglong2* w = reinterpret_cast<const ulonglong2*>(&sW2[k * OUT_CH]);
#pragma unroll
            for (int j = 0; j < OUT_CH / 4; j++) {
                ulonglong2 ww = w[j];
                FMA2(o[2 * j],     aa, ww.x, o[2 * j]);
                FMA2(o[2 * j + 1], aa, ww.y, o[2 * j + 1]);
            }
        }
    }

    // LeakyReLU + filtered scatter-max (round-6 epilogue)
    float* orow = out + (size_t)col * OUT_CH;
    const float4* oro = reinterpret_cast<const float4*>(orow);
#pragma unroll
    for (int q = 0; q < OUT_CH / 4; q++) {
        float v0, v1, v2, v3;
        upk2(v0, v1, o[2 * q]);
        upk2(v2, v3, o[2 * q + 1]);
        v0 = fmaxf(v0, 0.01f * v0);
        v1 = fmaxf(v1, 0.01f * v1);
        v2 = fmaxf(v2, 0.01f * v2);
        v3 = fmaxf(v3, 0.01f * v3);
        float4 cur = oro[q];                 // monotone max: stale read is safe
        if (v0 > cur.x) atomicMaxF(orow + 4 * q + 0, v0);
        if (v1 > cur.y) atomicMaxF(orow + 4 * q + 1, v1);
        if (v2 > cur.z) atomicMaxF(orow + 4 * q + 2, v2);
        if (v3 > cur.w) atomicMaxF(orow + 4 * q + 3, v3);
    }
}

// ---------------------------------------------------------------------------
// K3: finalize — -inf -> 0, elementwise max with x (float4)
// ---------------------------------------------------------------------------
__global__ void k_final(const float4* __restrict__ x, float4* __restrict__ out) {
    int i = blockIdx.x * blockDim.x + threadIdx.x;
    if (i >= N_NODES * OUT_CH / 4) return;
    float4 a = out[i];
    float4 b = x[i];
    if (__float_as_uint(a.x) == 0xFF800000u) a.x = 0.0f;
    if (__float_as_uint(a.y) == 0xFF800000u) a.y = 0.0f;
    if (__float_as_uint(a.z) == 0xFF800000u) a.z = 0.0f;
    if (__float_as_uint(a.w) == 0xFF800000u) a.w = 0.0f;
    a.x = fmaxf(a.x, b.x); a.y = fmaxf(a.y, b.y);
    a.z = fmaxf(a.z, b.z); a.w = fmaxf(a.w, b.w);
    out[i] = a;
}

// ---------------------------------------------------------------------------
extern "C" void kernel_launch(void* const* d_in, const int* in_sizes, int n_in,
                              void* d_out, int out_size) {
    const float* x         = (const float*)d_in[0];
    const int*   idx32     = (const int*)d_in[1];
    const float* edge_attr = (const float*)d_in[2];
    const float* W1        = (const float*)d_in[3];
    const float* b1        = (const float*)d_in[4];
    const float* W2        = (const float*)d_in[5];
    const float* b2        = (const float*)d_in[6];
    float* out = (float*)d_out;

    const int eg = (N_EDGES + 127) / 128;
    k_pre<<<592, 256>>>((const unsigned int*)d_in[1], (unsigned int*)d_out);
    k_node<<<(N_NODES + 127) / 128, 128>>>(x, W1, b1);
    k_e1<<<eg, 128>>>(idx32, edge_attr, W1);
    k_e2<<<eg, 128>>>(idx32, W2, b2, out);
    k_final<<<(N_NODES * OUT_CH / 4 + 255) / 256, 256>>>((const float4*)x, (float4*)out);
}